// round 5
// baseline (speedup 1.0000x reference)
#include <cuda_runtime.h>
#include <cstdint>

#define N_NODES 50000
#define DIM     256
#define NE      300000
#define NL      5
#define BN_EPS  1e-5f

#define BM 128
#define BN 64
#define BK 16        // k per main-loop iter (8 bf16x2 pairs)
#define ASTR 136     // As stride (uint32): (136*t+g)%32=(8t+g)%32 conflict-free
#define BSTR 72      // Bs stride (uint32): 72%32=8 -> conflict-free frag loads

// ---------------- scratch (static device globals; no runtime allocation) -----
__device__ float g_h[(size_t)N_NODES * DIM];
__device__ float g_z[(size_t)N_NODES * DIM];
__device__ float g_y[(size_t)N_NODES * DIM];
__device__ float g_stats[4 * DIM];
__device__ float g_ss1[2 * DIM];
__device__ float g_ss2[2 * DIM];

// ---------------- helpers ----------------------------------------------------
// Split (x0,x1) into packed bf16x2 hi and lo (lo = residual). low16 = x0.
__device__ __forceinline__ void split_bf16x2(float x0, float x1, uint32_t& hi, uint32_t& lo) {
    uint32_t h;
    asm("cvt.rn.bf16x2.f32 %0, %1, %2;" : "=r"(h) : "f"(x1), "f"(x0));
    float h0 = __uint_as_float(h << 16);
    float h1 = __uint_as_float(h & 0xffff0000u);
    asm("cvt.rn.bf16x2.f32 %0, %1, %2;" : "=r"(lo) : "f"(x1 - h1), "f"(x0 - h0));
    hi = h;
}

__device__ __forceinline__ void mma_bf16(float* d, const uint32_t* a, const uint32_t* b) {
    asm volatile(
        "mma.sync.aligned.m16n8k16.row.col.f32.bf16.bf16.f32 "
        "{%0,%1,%2,%3}, {%4,%5,%6,%7}, {%8,%9}, {%0,%1,%2,%3};"
        : "+f"(d[0]), "+f"(d[1]), "+f"(d[2]), "+f"(d[3])
        : "r"(a[0]), "r"(a[1]), "r"(a[2]), "r"(a[3]), "r"(b[0]), "r"(b[1]));
}

__global__ void k_zero_stats() {
    int i = blockIdx.x * 256 + threadIdx.x;
    if (i < 4 * DIM) g_stats[i] = 0.0f;
}

__global__ void k_init_z(const float* __restrict__ h, const float* __restrict__ eps, int l) {
    long i = (long)blockIdx.x * 256 + threadIdx.x;
    const long tot = (long)N_NODES * DIM / 4;
    if (i >= tot) return;
    float a = 1.0f + eps[l];
    float4 v = ((const float4*)h)[i];
    v.x *= a; v.y *= a; v.z *= a; v.w *= a;
    ((float4*)g_z)[i] = v;
}

__global__ void k_scatter(const float* __restrict__ h,
                          const int* __restrict__ src,
                          const int* __restrict__ dst) {
    long idx = (long)blockIdx.x * 256 + threadIdx.x;
    long e = idx >> 6;
    if (e >= NE) return;
    int c = (int)(idx & 63) << 2;
    int s = src[e], d = dst[e];
    float4 v = *(const float4*)(h + (size_t)s * DIM + c);
    v.x = fmaxf(v.x, 0.0f);
    v.y = fmaxf(v.y, 0.0f);
    v.z = fmaxf(v.z, 0.0f);
    v.w = fmaxf(v.w, 0.0f);
    float* p = g_z + (size_t)d * DIM + c;
    asm volatile("red.global.add.v4.f32 [%0], {%1,%2,%3,%4};"
                 :: "l"(p), "f"(v.x), "f"(v.y), "f"(v.z), "f"(v.w) : "memory");
}

// ---------------- 3xBF16 double-buffered tensor-core GEMM --------------------
// C[N,256] = f(A)[N,256] @ W[256,256] + bias; accumulates per-column sum /
// sum-of-squares into g_stats[slot]. TRANSFORM_A: relu(a*scale[k]+shift[k]).
template <bool TRANSFORM_A>
__global__ __launch_bounds__(256, 2)
void k_gemm(const float* __restrict__ A, const float* __restrict__ W,
            const float* __restrict__ bias, float* __restrict__ C,
            const float* __restrict__ ss, int slot) {
    __shared__ uint32_t As_hi[2][8][ASTR];
    __shared__ uint32_t As_lo[2][8][ASTR];
    __shared__ uint32_t Bs_hi[2][8][BSTR];
    __shared__ uint32_t Bs_lo[2][8][BSTR];
    __shared__ float s_sum[BN];
    __shared__ float s_sq[BN];

    const int tid  = threadIdx.x;
    const int lane = tid & 31;
    const int warp = tid >> 5;
    const int wr   = warp >> 1;      // 0..3 -> 32-row slab
    const int wc   = warp & 1;       // 0..1 -> 32-col slab
    const int g    = lane >> 2;      // 0..7
    const int t    = lane & 3;       // 0..3

    const int rowBase = blockIdx.y * BM;
    const int colBase = blockIdx.x * BN;

    if (tid < BN) { s_sum[tid] = 0.0f; s_sq[tid] = 0.0f; }

    // A map: 128 rows x 16 k; 2 threads/row, 8 k each (2 float4)
    const int arow = tid >> 1;
    const int ak   = (tid & 1) * 8;           // 0 or 8
    // B map (tid<128): 16 rows x 64 cols; thread covers rows 2bkp,2bkp+1 x 4 cols
    const int bkp  = tid >> 4;                // 0..7 (pair index) for tid<128
    const int bcol = (tid & 15) * 4;
    const bool b_ld = (tid < 128);

    const int agrow = rowBase + arow;
    const bool a_ok = (agrow < N_NODES);
    const float* Arow = A + (size_t)agrow * DIM;

    float acc[2][4][4];
#pragma unroll
    for (int mt = 0; mt < 2; mt++)
#pragma unroll
        for (int nt = 0; nt < 4; nt++)
#pragma unroll
            for (int j = 0; j < 4; j++) acc[mt][nt][j] = 0.0f;

    float4 av0, av1, br0, br1;

    // ---- fetch tile k0 into regs ----
    auto fetch = [&](int k0) {
        av0 = make_float4(0.f, 0.f, 0.f, 0.f);
        av1 = make_float4(0.f, 0.f, 0.f, 0.f);
        if (a_ok) {
            av0 = *(const float4*)(Arow + k0 + ak);
            av1 = *(const float4*)(Arow + k0 + ak + 4);
        }
        if (TRANSFORM_A) {
            int kc0 = k0 + ak, kc1 = k0 + ak + 4;
            av0.x = fmaxf(fmaf(av0.x, ss[kc0 + 0], ss[DIM + kc0 + 0]), 0.0f);
            av0.y = fmaxf(fmaf(av0.y, ss[kc0 + 1], ss[DIM + kc0 + 1]), 0.0f);
            av0.z = fmaxf(fmaf(av0.z, ss[kc0 + 2], ss[DIM + kc0 + 2]), 0.0f);
            av0.w = fmaxf(fmaf(av0.w, ss[kc0 + 3], ss[DIM + kc0 + 3]), 0.0f);
            av1.x = fmaxf(fmaf(av1.x, ss[kc1 + 0], ss[DIM + kc1 + 0]), 0.0f);
            av1.y = fmaxf(fmaf(av1.y, ss[kc1 + 1], ss[DIM + kc1 + 1]), 0.0f);
            av1.z = fmaxf(fmaf(av1.z, ss[kc1 + 2], ss[DIM + kc1 + 2]), 0.0f);
            av1.w = fmaxf(fmaf(av1.w, ss[kc1 + 3], ss[DIM + kc1 + 3]), 0.0f);
        }
        if (b_ld) {
            br0 = *(const float4*)(W + (size_t)(k0 + 2 * bkp)     * DIM + colBase + bcol);
            br1 = *(const float4*)(W + (size_t)(k0 + 2 * bkp + 1) * DIM + colBase + bcol);
        }
    };

    // ---- convert staged regs into smem buffer ----
    auto stash = [&](int buf) {
        uint32_t hi, lo;
        int kp = ak >> 1;                                 // 0 or 4
        split_bf16x2(av0.x, av0.y, hi, lo);
        As_hi[buf][kp][arow] = hi;     As_lo[buf][kp][arow] = lo;
        split_bf16x2(av0.z, av0.w, hi, lo);
        As_hi[buf][kp + 1][arow] = hi; As_lo[buf][kp + 1][arow] = lo;
        split_bf16x2(av1.x, av1.y, hi, lo);
        As_hi[buf][kp + 2][arow] = hi; As_lo[buf][kp + 2][arow] = lo;
        split_bf16x2(av1.z, av1.w, hi, lo);
        As_hi[buf][kp + 3][arow] = hi; As_lo[buf][kp + 3][arow] = lo;
        if (b_ld) {
            uint32_t ph[4], pl[4];
            split_bf16x2(br0.x, br1.x, ph[0], pl[0]);
            split_bf16x2(br0.y, br1.y, ph[1], pl[1]);
            split_bf16x2(br0.z, br1.z, ph[2], pl[2]);
            split_bf16x2(br0.w, br1.w, ph[3], pl[3]);
            *(uint4*)&Bs_hi[buf][bkp][bcol] = *(uint4*)ph;
            *(uint4*)&Bs_lo[buf][bkp][bcol] = *(uint4*)pl;
        }
    };

    fetch(0);
    stash(0);
    __syncthreads();

    const int mrow = wr * 32;
    const int ncol = wc * 32;

#pragma unroll 1
    for (int it = 0; it < DIM / BK; it++) {
        const int cur = it & 1;
        if (it < DIM / BK - 1) fetch((it + 1) * BK);   // prefetch next tile

        // ---- compute from buffer cur ----
        uint32_t ahi[2][4], alo[2][4], bhi[4][2], blo[4][2];
#pragma unroll
        for (int mt = 0; mt < 2; mt++) {
            int r = mrow + mt * 16 + g;
            ahi[mt][0] = As_hi[cur][t][r];
            ahi[mt][1] = As_hi[cur][t][r + 8];
            ahi[mt][2] = As_hi[cur][t + 4][r];
            ahi[mt][3] = As_hi[cur][t + 4][r + 8];
            alo[mt][0] = As_lo[cur][t][r];
            alo[mt][1] = As_lo[cur][t][r + 8];
            alo[mt][2] = As_lo[cur][t + 4][r];
            alo[mt][3] = As_lo[cur][t + 4][r + 8];
        }
#pragma unroll
        for (int nt = 0; nt < 4; nt++) {
            int c = ncol + nt * 8 + g;
            bhi[nt][0] = Bs_hi[cur][t][c];
            bhi[nt][1] = Bs_hi[cur][t + 4][c];
            blo[nt][0] = Bs_lo[cur][t][c];
            blo[nt][1] = Bs_lo[cur][t + 4][c];
        }
#pragma unroll
        for (int mt = 0; mt < 2; mt++)
#pragma unroll
            for (int nt = 0; nt < 4; nt++)
                mma_bf16(acc[mt][nt], ahi[mt], bhi[nt]);
#pragma unroll
        for (int mt = 0; mt < 2; mt++)
#pragma unroll
            for (int nt = 0; nt < 4; nt++)
                mma_bf16(acc[mt][nt], ahi[mt], blo[nt]);
#pragma unroll
        for (int mt = 0; mt < 2; mt++)
#pragma unroll
            for (int nt = 0; nt < 4; nt++)
                mma_bf16(acc[mt][nt], alo[mt], bhi[nt]);

        if (it < DIM / BK - 1) stash(cur ^ 1);
        __syncthreads();
    }

    // ---- epilogue: bias, store, per-column BN stats ----
    float bs[4][2];
#pragma unroll
    for (int nt = 0; nt < 4; nt++) {
        int c = colBase + ncol + nt * 8 + 2 * t;
        bs[nt][0] = bias[c];
        bs[nt][1] = bias[c + 1];
    }

    float csum[4][2], csq[4][2];
#pragma unroll
    for (int nt = 0; nt < 4; nt++) {
        csum[nt][0] = 0.f; csum[nt][1] = 0.f;
        csq[nt][0] = 0.f;  csq[nt][1] = 0.f;
    }

#pragma unroll
    for (int mt = 0; mt < 2; mt++) {
        int r0 = rowBase + mrow + mt * 16 + g;
        int r1 = r0 + 8;
        bool ok0 = (r0 < N_NODES), ok1 = (r1 < N_NODES);
#pragma unroll
        for (int nt = 0; nt < 4; nt++) {
            int c = colBase + ncol + nt * 8 + 2 * t;
            float v0 = acc[mt][nt][0] + bs[nt][0];
            float v1 = acc[mt][nt][1] + bs[nt][1];
            float v2 = acc[mt][nt][2] + bs[nt][0];
            float v3 = acc[mt][nt][3] + bs[nt][1];
            if (ok0) {
                *(float2*)(C + (size_t)r0 * DIM + c) = make_float2(v0, v1);
                csum[nt][0] += v0; csq[nt][0] += v0 * v0;
                csum[nt][1] += v1; csq[nt][1] += v1 * v1;
            }
            if (ok1) {
                *(float2*)(C + (size_t)r1 * DIM + c) = make_float2(v2, v3);
                csum[nt][0] += v2; csq[nt][0] += v2 * v2;
                csum[nt][1] += v3; csq[nt][1] += v3 * v3;
            }
        }
    }
#pragma unroll
    for (int nt = 0; nt < 4; nt++) {
        int lc = ncol + nt * 8 + 2 * t;
        atomicAdd(&s_sum[lc],     csum[nt][0]);
        atomicAdd(&s_sq[lc],      csq[nt][0]);
        atomicAdd(&s_sum[lc + 1], csum[nt][1]);
        atomicAdd(&s_sq[lc + 1],  csq[nt][1]);
    }
    __syncthreads();
    if (tid < BN) {
        atomicAdd(&g_stats[slot * 512 +       colBase + tid], s_sum[tid]);
        atomicAdd(&g_stats[slot * 512 + 256 + colBase + tid], s_sq[tid]);
    }
}

__global__ void k_finalize(int slot, const float* __restrict__ gamma,
                           const float* __restrict__ beta, float* __restrict__ out_ss) {
    int c = threadIdx.x;
    if (c >= DIM) return;
    float s = g_stats[slot * 512 + c];
    float q = g_stats[slot * 512 + 256 + c];
    float mean = s * (1.0f / N_NODES);
    float var  = q * (1.0f / N_NODES) - mean * mean;
    float istd = rsqrtf(var + BN_EPS);
    float sc = gamma[c] * istd;
    out_ss[c]       = sc;
    out_ss[DIM + c] = beta[c] - mean * sc;
}

// out_h = BN2(z) (+relu); if next_l >= 0 also g_z = (1+eps[next_l]) * out_h
__global__ void k_apply_init(float* __restrict__ out_h, int do_relu,
                             const float* __restrict__ eps, int next_l) {
    long i = (long)blockIdx.x * 256 + threadIdx.x;
    const long tot = (long)N_NODES * DIM / 4;
    if (i >= tot) return;
    int c = (int)(i & 63) << 2;
    float4 v = ((const float4*)g_z)[i];
    v.x = fmaf(v.x, g_ss2[c + 0], g_ss2[DIM + c + 0]);
    v.y = fmaf(v.y, g_ss2[c + 1], g_ss2[DIM + c + 1]);
    v.z = fmaf(v.z, g_ss2[c + 2], g_ss2[DIM + c + 2]);
    v.w = fmaf(v.w, g_ss2[c + 3], g_ss2[DIM + c + 3]);
    if (do_relu) {
        v.x = fmaxf(v.x, 0.0f);
        v.y = fmaxf(v.y, 0.0f);
        v.z = fmaxf(v.z, 0.0f);
        v.w = fmaxf(v.w, 0.0f);
    }
    ((float4*)out_h)[i] = v;
    if (next_l >= 0) {
        float a = 1.0f + eps[next_l];
        float4 z = make_float4(v.x * a, v.y * a, v.z * a, v.w * a);
        ((float4*)g_z)[i] = z;
    }
}

// ---------------- host-side orchestration ------------------------------------
extern "C" void kernel_launch(void* const* d_in, const int* in_sizes, int n_in,
                              void* d_out, int out_size) {
    const float* x    = (const float*)d_in[0];
    const int*   src  = (const int*)  d_in[1];
    const int*   dst  = (const int*)  d_in[2];
    const float* W1   = (const float*)d_in[3];
    const float* b1   = (const float*)d_in[4];
    const float* g1   = (const float*)d_in[5];
    const float* bt1  = (const float*)d_in[6];
    const float* W2   = (const float*)d_in[7];
    const float* b2   = (const float*)d_in[8];
    const float* eps  = (const float*)d_in[9];
    const float* bn_g = (const float*)d_in[10];
    const float* bn_b = (const float*)d_in[11];
    float* out = (float*)d_out;

    float *hp, *zp, *yp, *ss1p, *ss2p;
    cudaGetSymbolAddress((void**)&hp,   g_h);
    cudaGetSymbolAddress((void**)&zp,   g_z);
    cudaGetSymbolAddress((void**)&yp,   g_y);
    cudaGetSymbolAddress((void**)&ss1p, g_ss1);
    cudaGetSymbolAddress((void**)&ss2p, g_ss2);

    const long ew_items = (long)N_NODES * DIM / 4;
    const int  ew_grid  = (int)((ew_items + 255) / 256);
    const long sc_items = (long)NE * (DIM / 4);
    const int  sc_grid  = (int)((sc_items + 255) / 256);
    const dim3 gemm_grid(DIM / BN, (N_NODES + BM - 1) / BM);   // (4, 391)

    for (int l = 0; l < NL; l++) {
        const float* h = (l == 0) ? x : hp;

        k_zero_stats<<<4, 256>>>();
        if (l == 0) k_init_z<<<ew_grid, 256>>>(x, eps, 0);
        k_scatter<<<sc_grid, 256>>>(h, src, dst);

        k_gemm<false><<<gemm_grid, 256>>>(zp, W1 + (size_t)l * DIM * DIM,
                                          b1 + (size_t)l * DIM, yp, nullptr, 0);
        k_finalize<<<1, 256>>>(0, g1 + (size_t)l * DIM, bt1 + (size_t)l * DIM, ss1p);

        k_gemm<true><<<gemm_grid, 256>>>(yp, W2 + (size_t)l * DIM * DIM,
                                         b2 + (size_t)l * DIM, zp, ss1p, 1);
        k_finalize<<<1, 256>>>(1, bn_g + (size_t)l * DIM, bn_b + (size_t)l * DIM, ss2p);

        k_apply_init<<<ew_grid, 256>>>((l == NL - 1) ? out : hp,
                                       (l < NL - 1) ? 1 : 0, eps,
                                       (l < NL - 1) ? l + 1 : -1);
    }
}

// round 6
// speedup vs baseline: 1.4007x; 1.4007x over previous
#include <cuda_runtime.h>
#include <cstdint>

#define N_NODES 50000
#define DIM     256
#define NE      300000
#define NL      5
#define BN_EPS  1e-5f

#define BM 128
#define BN 128
#define BK 16        // k per main-loop iter (8 bf16x2 pairs)
#define SSTRIDE 136  // uint32 stride: (136*t + g) % 32 = (8t+g)%32 -> conflict-free

// ---------------- scratch (static device globals; no runtime allocation) -----
__device__ float g_h[(size_t)N_NODES * DIM];
__device__ float g_z[(size_t)N_NODES * DIM];
__device__ float g_y[(size_t)N_NODES * DIM];
__device__ float g_stats[4 * DIM];   // zero at module load; k_finalize re-zeros
__device__ float g_ss1[2 * DIM];
__device__ float g_ss2[2 * DIM];

// ---------------- helpers ----------------------------------------------------
// Split (x0,x1) into packed bf16x2 hi and lo (lo = residual). low16 = x0.
__device__ __forceinline__ void split_bf16x2(float x0, float x1, uint32_t& hi, uint32_t& lo) {
    uint32_t h;
    asm("cvt.rn.bf16x2.f32 %0, %1, %2;" : "=r"(h) : "f"(x1), "f"(x0));
    float h0 = __uint_as_float(h << 16);
    float h1 = __uint_as_float(h & 0xffff0000u);
    asm("cvt.rn.bf16x2.f32 %0, %1, %2;" : "=r"(lo) : "f"(x1 - h1), "f"(x0 - h0));
    hi = h;
}

__device__ __forceinline__ void mma_bf16(float* d, const uint32_t* a, const uint32_t* b) {
    asm volatile(
        "mma.sync.aligned.m16n8k16.row.col.f32.bf16.bf16.f32 "
        "{%0,%1,%2,%3}, {%4,%5,%6,%7}, {%8,%9}, {%0,%1,%2,%3};"
        : "+f"(d[0]), "+f"(d[1]), "+f"(d[2]), "+f"(d[3])
        : "r"(a[0]), "r"(a[1]), "r"(a[2]), "r"(a[3]), "r"(b[0]), "r"(b[1]));
}

__global__ void k_init_z(const float* __restrict__ h, const float* __restrict__ eps, int l) {
    long i = (long)blockIdx.x * 256 + threadIdx.x;
    const long tot = (long)N_NODES * DIM / 4;
    if (i >= tot) return;
    float a = 1.0f + eps[l];
    float4 v = ((const float4*)h)[i];
    v.x *= a; v.y *= a; v.z *= a; v.w *= a;
    ((float4*)g_z)[i] = v;
}

__global__ void k_scatter(const float* __restrict__ h,
                          const int* __restrict__ src,
                          const int* __restrict__ dst) {
    long idx = (long)blockIdx.x * 256 + threadIdx.x;
    long e = idx >> 6;
    if (e >= NE) return;
    int c = (int)(idx & 63) << 2;
    int s = src[e], d = dst[e];
    float4 v = *(const float4*)(h + (size_t)s * DIM + c);
    v.x = fmaxf(v.x, 0.0f);
    v.y = fmaxf(v.y, 0.0f);
    v.z = fmaxf(v.z, 0.0f);
    v.w = fmaxf(v.w, 0.0f);
    float* p = g_z + (size_t)d * DIM + c;
    asm volatile("red.global.add.v4.f32 [%0], {%1,%2,%3,%4};"
                 :: "l"(p), "f"(v.x), "f"(v.y), "f"(v.z), "f"(v.w) : "memory");
}

// ---------------- 3xBF16 tensor-core GEMM, latency-hiding pipeline ----------
// C[N,256] = f(A)[N,256] @ W[256,256] + bias; accumulates per-column sum /
// sum-of-squares into g_stats[slot]. TRANSFORM_A: relu(a*scale[k]+shift[k]).
template <bool TRANSFORM_A>
__global__ __launch_bounds__(256, 2)
void k_gemm(const float* __restrict__ A, const float* __restrict__ W,
            const float* __restrict__ bias, float* __restrict__ C,
            const float* __restrict__ ss, int slot) {
    // [k-pair][row/col] packed bf16x2 (pair = k even|odd)
    __shared__ uint32_t As_hi[8][SSTRIDE];
    __shared__ uint32_t As_lo[8][SSTRIDE];
    __shared__ uint32_t Bs_hi[8][SSTRIDE];
    __shared__ uint32_t Bs_lo[8][SSTRIDE];
    __shared__ float s_sum[BN];
    __shared__ float s_sq[BN];

    const int tid  = threadIdx.x;
    const int lane = tid & 31;
    const int warp = tid >> 5;
    const int wr   = warp >> 2;      // 0..1 -> 64-row slab
    const int wc   = warp & 3;       // 0..3 -> 32-col slab
    const int g    = lane >> 2;      // 0..7
    const int t    = lane & 3;       // 0..3

    const int rowBase = blockIdx.y * BM;
    const int colBase = blockIdx.x * BN;

    if (tid < BN) { s_sum[tid] = 0.0f; s_sq[tid] = 0.0f; }

    // A load map: 128 rows x 16 k; 2 threads/row, 8 k each (2 float4)
    const int arow = tid >> 1;
    const int ak   = (tid & 1) * 4;       // 0 or 4 (second vec at +8)
    // B load map: 16 k x 128 cols; thread covers k rows (bk2, bk2+1) x 4 cols
    const int bk2  = (tid >> 5) * 2;      // 0,2,..,14
    const int bkp  = tid >> 5;            // pair index 0..7
    const int bcol = (tid & 31) * 4;

    const int agrow = rowBase + arow;
    const bool a_ok = (agrow < N_NODES);
    const float* Arow = A + (size_t)agrow * DIM;

    float acc[4][4][4];
#pragma unroll
    for (int mt = 0; mt < 4; mt++)
#pragma unroll
        for (int nt = 0; nt < 4; nt++)
#pragma unroll
            for (int j = 0; j < 4; j++) acc[mt][nt][j] = 0.0f;

    float4 av0, av1, br0, br1;   // staging regs (live across compute)

    auto fetch = [&](int k0) {
        av0 = make_float4(0.f, 0.f, 0.f, 0.f);
        av1 = make_float4(0.f, 0.f, 0.f, 0.f);
        if (a_ok) {
            av0 = *(const float4*)(Arow + k0 + ak);
            av1 = *(const float4*)(Arow + k0 + ak + 8);
        }
        if (TRANSFORM_A) {
            int kc0 = k0 + ak, kc1 = k0 + ak + 8;
            av0.x = fmaxf(fmaf(av0.x, ss[kc0 + 0], ss[DIM + kc0 + 0]), 0.0f);
            av0.y = fmaxf(fmaf(av0.y, ss[kc0 + 1], ss[DIM + kc0 + 1]), 0.0f);
            av0.z = fmaxf(fmaf(av0.z, ss[kc0 + 2], ss[DIM + kc0 + 2]), 0.0f);
            av0.w = fmaxf(fmaf(av0.w, ss[kc0 + 3], ss[DIM + kc0 + 3]), 0.0f);
            av1.x = fmaxf(fmaf(av1.x, ss[kc1 + 0], ss[DIM + kc1 + 0]), 0.0f);
            av1.y = fmaxf(fmaf(av1.y, ss[kc1 + 1], ss[DIM + kc1 + 1]), 0.0f);
            av1.z = fmaxf(fmaf(av1.z, ss[kc1 + 2], ss[DIM + kc1 + 2]), 0.0f);
            av1.w = fmaxf(fmaf(av1.w, ss[kc1 + 3], ss[DIM + kc1 + 3]), 0.0f);
        }
        br0 = *(const float4*)(W + (size_t)(k0 + bk2)     * DIM + colBase + bcol);
        br1 = *(const float4*)(W + (size_t)(k0 + bk2 + 1) * DIM + colBase + bcol);
    };

    auto stash = [&]() {
        uint32_t hi, lo;
        int kp = ak >> 1;                          // 0 or 2
        split_bf16x2(av0.x, av0.y, hi, lo);
        As_hi[kp][arow] = hi;     As_lo[kp][arow] = lo;
        split_bf16x2(av0.z, av0.w, hi, lo);
        As_hi[kp + 1][arow] = hi; As_lo[kp + 1][arow] = lo;
        split_bf16x2(av1.x, av1.y, hi, lo);
        As_hi[kp + 4][arow] = hi; As_lo[kp + 4][arow] = lo;
        split_bf16x2(av1.z, av1.w, hi, lo);
        As_hi[kp + 5][arow] = hi; As_lo[kp + 5][arow] = lo;
        {
            uint32_t ph[4], pl[4];
            split_bf16x2(br0.x, br1.x, ph[0], pl[0]);
            split_bf16x2(br0.y, br1.y, ph[1], pl[1]);
            split_bf16x2(br0.z, br1.z, ph[2], pl[2]);
            split_bf16x2(br0.w, br1.w, ph[3], pl[3]);
            *(uint4*)&Bs_hi[bkp][bcol] = *(uint4*)ph;
            *(uint4*)&Bs_lo[bkp][bcol] = *(uint4*)pl;
        }
    };

    const int mrow = wr * 64;
    const int ncol = wc * 32;

    fetch(0);   // prologue

#pragma unroll 1
    for (int it = 0; it < DIM / BK; it++) {
        __syncthreads();                  // prev compute done -> safe to overwrite
        stash();                          // staged regs -> smem (hi/lo split)
        __syncthreads();                  // tile visible
        if (it < DIM / BK - 1) fetch((it + 1) * BK);   // loads fly under compute

        // ---- compute tile it ----
        uint32_t ahi[4][4], bhi[4][2], blo[4][2];
#pragma unroll
        for (int mt = 0; mt < 4; mt++) {
            int r = mrow + mt * 16 + g;
            ahi[mt][0] = As_hi[t][r];
            ahi[mt][1] = As_hi[t][r + 8];
            ahi[mt][2] = As_hi[t + 4][r];
            ahi[mt][3] = As_hi[t + 4][r + 8];
        }
#pragma unroll
        for (int nt = 0; nt < 4; nt++) {
            int c = ncol + nt * 8 + g;
            bhi[nt][0] = Bs_hi[t][c];
            bhi[nt][1] = Bs_hi[t + 4][c];
            blo[nt][0] = Bs_lo[t][c];
            blo[nt][1] = Bs_lo[t + 4][c];
        }
        // pass 1: hi*hi
#pragma unroll
        for (int mt = 0; mt < 4; mt++)
#pragma unroll
            for (int nt = 0; nt < 4; nt++)
                mma_bf16(acc[mt][nt], ahi[mt], bhi[nt]);
        // pass 2: hi*lo
#pragma unroll
        for (int mt = 0; mt < 4; mt++)
#pragma unroll
            for (int nt = 0; nt < 4; nt++)
                mma_bf16(acc[mt][nt], ahi[mt], blo[nt]);
        // pass 3: lo*hi
        uint32_t alo[4][4];
#pragma unroll
        for (int mt = 0; mt < 4; mt++) {
            int r = mrow + mt * 16 + g;
            alo[mt][0] = As_lo[t][r];
            alo[mt][1] = As_lo[t][r + 8];
            alo[mt][2] = As_lo[t + 4][r];
            alo[mt][3] = As_lo[t + 4][r + 8];
        }
#pragma unroll
        for (int mt = 0; mt < 4; mt++)
#pragma unroll
            for (int nt = 0; nt < 4; nt++)
                mma_bf16(acc[mt][nt], alo[mt], bhi[nt]);
    }

    // ---- epilogue: bias, store, per-column BN stats ----
    float bs[4][2];
#pragma unroll
    for (int nt = 0; nt < 4; nt++) {
        int c = colBase + ncol + nt * 8 + 2 * t;
        bs[nt][0] = bias[c];
        bs[nt][1] = bias[c + 1];
    }

    float csum[4][2], csq[4][2];
#pragma unroll
    for (int nt = 0; nt < 4; nt++) {
        csum[nt][0] = 0.f; csum[nt][1] = 0.f;
        csq[nt][0] = 0.f;  csq[nt][1] = 0.f;
    }

#pragma unroll
    for (int mt = 0; mt < 4; mt++) {
        int r0 = rowBase + mrow + mt * 16 + g;
        int r1 = r0 + 8;
        bool ok0 = (r0 < N_NODES), ok1 = (r1 < N_NODES);
#pragma unroll
        for (int nt = 0; nt < 4; nt++) {
            int c = colBase + ncol + nt * 8 + 2 * t;
            float v0 = acc[mt][nt][0] + bs[nt][0];
            float v1 = acc[mt][nt][1] + bs[nt][1];
            float v2 = acc[mt][nt][2] + bs[nt][0];
            float v3 = acc[mt][nt][3] + bs[nt][1];
            if (ok0) {
                *(float2*)(C + (size_t)r0 * DIM + c) = make_float2(v0, v1);
                csum[nt][0] += v0; csq[nt][0] += v0 * v0;
                csum[nt][1] += v1; csq[nt][1] += v1 * v1;
            }
            if (ok1) {
                *(float2*)(C + (size_t)r1 * DIM + c) = make_float2(v2, v3);
                csum[nt][0] += v2; csq[nt][0] += v2 * v2;
                csum[nt][1] += v3; csq[nt][1] += v3 * v3;
            }
        }
    }
#pragma unroll
    for (int nt = 0; nt < 4; nt++) {
        int lc = ncol + nt * 8 + 2 * t;
        atomicAdd(&s_sum[lc],     csum[nt][0]);
        atomicAdd(&s_sq[lc],      csq[nt][0]);
        atomicAdd(&s_sum[lc + 1], csum[nt][1]);
        atomicAdd(&s_sq[lc + 1],  csq[nt][1]);
    }
    __syncthreads();
    if (tid < BN) {
        atomicAdd(&g_stats[slot * 512 +       colBase + tid], s_sum[tid]);
        atomicAdd(&g_stats[slot * 512 + 256 + colBase + tid], s_sq[tid]);
    }
}

// stats -> scale/shift; re-zeros its stats slot for the next use/replay
__global__ void k_finalize(int slot, const float* __restrict__ gamma,
                           const float* __restrict__ beta, float* __restrict__ out_ss) {
    int c = threadIdx.x;
    if (c >= DIM) return;
    float s = g_stats[slot * 512 + c];
    float q = g_stats[slot * 512 + 256 + c];
    g_stats[slot * 512 + c] = 0.0f;
    g_stats[slot * 512 + 256 + c] = 0.0f;
    float mean = s * (1.0f / N_NODES);
    float var  = q * (1.0f / N_NODES) - mean * mean;
    float istd = rsqrtf(var + BN_EPS);
    float sc = gamma[c] * istd;
    out_ss[c]       = sc;
    out_ss[DIM + c] = beta[c] - mean * sc;
}

// out_h = BN2(z) (+relu); if next_l >= 0 also g_z = (1+eps[next_l]) * out_h
__global__ void k_apply_init(float* __restrict__ out_h, int do_relu,
                             const float* __restrict__ eps, int next_l) {
    long i = (long)blockIdx.x * 256 + threadIdx.x;
    const long tot = (long)N_NODES * DIM / 4;
    if (i >= tot) return;
    int c = (int)(i & 63) << 2;
    float4 v = ((const float4*)g_z)[i];
    v.x = fmaf(v.x, g_ss2[c + 0], g_ss2[DIM + c + 0]);
    v.y = fmaf(v.y, g_ss2[c + 1], g_ss2[DIM + c + 1]);
    v.z = fmaf(v.z, g_ss2[c + 2], g_ss2[DIM + c + 2]);
    v.w = fmaf(v.w, g_ss2[c + 3], g_ss2[DIM + c + 3]);
    if (do_relu) {
        v.x = fmaxf(v.x, 0.0f);
        v.y = fmaxf(v.y, 0.0f);
        v.z = fmaxf(v.z, 0.0f);
        v.w = fmaxf(v.w, 0.0f);
    }
    ((float4*)out_h)[i] = v;
    if (next_l >= 0) {
        float a = 1.0f + eps[next_l];
        float4 z = make_float4(v.x * a, v.y * a, v.z * a, v.w * a);
        ((float4*)g_z)[i] = z;
    }
}

// ---------------- host-side orchestration ------------------------------------
extern "C" void kernel_launch(void* const* d_in, const int* in_sizes, int n_in,
                              void* d_out, int out_size) {
    const float* x    = (const float*)d_in[0];
    const int*   src  = (const int*)  d_in[1];
    const int*   dst  = (const int*)  d_in[2];
    const float* W1   = (const float*)d_in[3];
    const float* b1   = (const float*)d_in[4];
    const float* g1   = (const float*)d_in[5];
    const float* bt1  = (const float*)d_in[6];
    const float* W2   = (const float*)d_in[7];
    const float* b2   = (const float*)d_in[8];
    const float* eps  = (const float*)d_in[9];
    const float* bn_g = (const float*)d_in[10];
    const float* bn_b = (const float*)d_in[11];
    float* out = (float*)d_out;

    float *hp, *zp, *yp, *ss1p, *ss2p;
    cudaGetSymbolAddress((void**)&hp,   g_h);
    cudaGetSymbolAddress((void**)&zp,   g_z);
    cudaGetSymbolAddress((void**)&yp,   g_y);
    cudaGetSymbolAddress((void**)&ss1p, g_ss1);
    cudaGetSymbolAddress((void**)&ss2p, g_ss2);

    const long ew_items = (long)N_NODES * DIM / 4;
    const int  ew_grid  = (int)((ew_items + 255) / 256);
    const long sc_items = (long)NE * (DIM / 4);
    const int  sc_grid  = (int)((sc_items + 255) / 256);
    const dim3 gemm_grid(DIM / BN, (N_NODES + BM - 1) / BM);   // (2, 391)

    for (int l = 0; l < NL; l++) {
        const float* h = (l == 0) ? x : hp;

        if (l == 0) k_init_z<<<ew_grid, 256>>>(x, eps, 0);
        k_scatter<<<sc_grid, 256>>>(h, src, dst);

        k_gemm<false><<<gemm_grid, 256>>>(zp, W1 + (size_t)l * DIM * DIM,
                                          b1 + (size_t)l * DIM, yp, nullptr, 0);
        k_finalize<<<1, 256>>>(0, g1 + (size_t)l * DIM, bt1 + (size_t)l * DIM, ss1p);

        k_gemm<true><<<gemm_grid, 256>>>(yp, W2 + (size_t)l * DIM * DIM,
                                         b2 + (size_t)l * DIM, zp, ss1p, 1);
        k_finalize<<<1, 256>>>(1, bn_g + (size_t)l * DIM, bn_b + (size_t)l * DIM, ss2p);

        k_apply_init<<<ew_grid, 256>>>((l == NL - 1) ? out : hp,
                                       (l < NL - 1) ? 1 : 0, eps,
                                       (l < NL - 1) ? l + 1 : -1);
    }
}